// round 13
// baseline (speedup 1.0000x reference)
#include <cuda_runtime.h>

// Profile-HMM forward NLL + KLD -- wavefront, scaled linear domain,
// TWO WARPS PER BATCH ELEMENT. 512 CTAs x 64 threads: warp A owns k=1..32,
// warp B owns k=33..64 (one column per lane). The k=32->33 boundary moves
// through a double-buffered smem float4 with one __syncthreads per diagonal.
// Deferred CTA-uniform power-of-2 rescale every 4 diagonals (redux.sync +
// two-window-lagged cross-warp max exchange in smem). All scaling exact.

#define FULLMASK 0xffffffffu
#define LN2 0.69314718055994531f

__device__ float g_vb[512];
__device__ unsigned int g_cnt = 0;

__device__ __forceinline__ unsigned warp_max_u32(unsigned v) {
    unsigned r;
    asm volatile("redux.sync.max.u32 %0, %1, 0xffffffff;" : "=r"(r) : "r"(v));
    return r;
}

__global__ void __launch_bounds__(64) phmm_kernel(
    const int*   __restrict__ binput,    // (B, 256)
    const float* __restrict__ trans,     // (B, 65, 7) log-probs (nats)
    const float* __restrict__ emis,      // (B, 64, 4) log-probs (nats)
    const float* __restrict__ mus,       // (B, 16)
    const float* __restrict__ logvars,   // (B, 16)
    float*       __restrict__ out)
{
    constexpr int L = 256;
    constexpr int K = 64;
    const int b    = blockIdx.x;
    const int tid  = threadIdx.x;
    const int w    = tid >> 5;
    const int lane = tid & 31;
    const int gk   = tid;               // this lane owns column k = gk+1 (1..64)

    __shared__ int    s_co_p[416];      // 64 front-pad + 256 symbols (sym*64) + pad
    __shared__ float  esh[256];         // [4 sym][64 k] emission probs
    __shared__ float4 bbuf[2];          // boundary k=32 {M,I,D,_}, double buffer
    __shared__ float  mbuf[2][2];       // per-warp window max, double buffer

    const int* bi = binput + b * L;
    for (int i = tid; i < 416; i += 64) {
        int v = 0;
        if (i >= 64 && i < 320) v = bi[i - 64] << 6;   // symbol * 64
        s_co_p[i] = v;
    }
    const float* em = emis + b * 256;
#pragma unroll
    for (int c = 0; c < 4; ++c)
        esh[c * 64 + gk] = expf(em[gk * 4 + c]);

    const float M00 = 1.152921504606847e18f;           // 1.0 * 2^60
    if (tid < 2) bbuf[tid] = make_float4(0.f, 0.f, 0.f, 0.f);
    if (tid < 4) mbuf[tid >> 1][tid & 1] = M00;

    const float* a  = trans + b * 65 * 7;
    const float* r0 = a + gk * 7;        // transition row k-1
    const float* r1 = r0 + 7;            // row k
    // indices: M2M=0, M2I=1, M2D=2, I2M=3, I2I=4, D2M=5, D2D=6; LOG_Q folded.
    const float aMM = expf(r0[0]), aMD = expf(r0[2]);
    const float aIM = expf(r0[3]), aDM = expf(r0[5]), aDD = expf(r0[6]);
    const float aMI = 0.25f * expf(r1[1]), aII = 0.25f * expf(r1[4]);
    const float aMI0 = 0.25f * expf(a[1]), aII0 = 0.25f * expf(a[4]);  // row 0
    __syncthreads();

    // per-lane state: c (own, diag t-1), q (neighbor diag t-2), n (neighbor t-1)
    float cM = 0.f, cI = 0.f, cD = 0.f;
    float qM = 0.f, qI = 0.f, qD = 0.f;
    float nM = 0.f, nI = 0.f, nD = 0.f;
    float inj   = exp2f(-84.26950408889634f);   // e^-100 * 2^60 (NEG boundary)
    float k0I   = inj;                          // I(0,0) = NEG
    float mprev = M00;                          // M(0,0)
    int   Sacc  = 60;
    float sc_ap = 1.0f;  int se_ap = 0;         // deferred rescale
    float m_prev = M00;                         // own window max (lagged)

    if (tid == 0) { nM = M00; nI = inj; nD = inj; }   // A lane0: k=0 col @ diag 0

    // emission pipeline priming: P = e(t=1); off_p feeds e(t=2)
    int   off_p = s_co_p[64 - gk];
    float P     = esh[s_co_p[63 - gk] + gk];

    // ================= phase 1: t = 1..64 (boundary forcing live) ==========
#pragma unroll 4
    for (int t = 1; t <= 64; ++t) {
        const int l = t - gk - 1;
        float Mg = P * fmaf(aDM, qD, fmaf(aIM, qI, aMM * qM));
        float Ig = fmaf(aII, cI, aMI * cM);
        float Dn = fmaf(aDD, nD, aMD * nM);
        float Mn = (l == 0) ? inj : Mg;
        float In = (l == 0) ? inj : Ig;

        qM = nM; qI = nI; qD = nD;
        cM = Mn; cI = In; cD = Dn;

        k0I = fmaf(aII0, k0I, aMI0 * mprev);    // k=0 column (uniform, all threads)
        mprev = inj;

        nM = __shfl_up_sync(FULLMASK, cM, 1);
        nI = __shfl_up_sync(FULLMASK, cI, 1);
        nD = __shfl_up_sync(FULLMASK, cD, 1);
        if (tid == 31) bbuf[t & 1] = make_float4(cM, cI, cD, 0.f);
        __syncthreads();
        if (tid == 0)        { nM = mprev; nI = k0I; nD = inj; }
        else if (tid == 32)  { float4 v = bbuf[t & 1]; nM = v.x; nI = v.y; nD = v.z; }

        P = esh[off_p + gk];
        off_p = s_co_p[t - gk + 64];

        if ((t & 3) == 0) {
            cM *= sc_ap; cI *= sc_ap; cD *= sc_ap;
            qM *= sc_ap; qI *= sc_ap; qD *= sc_ap;
            nM *= sc_ap; nI *= sc_ap; nD *= sc_ap;
            k0I *= sc_ap; mprev *= sc_ap; inj *= sc_ap;
            Sacc += se_ap;
            float m = fmaxf(fmaxf(cM, cI), fmaxf(cD, k0I));
            m = __uint_as_float(warp_max_u32(__float_as_uint(m)));
            const int p = (t >> 2) & 1;
            if (lane == 0) mbuf[p][w] = m;
            const float comb = fmaxf(m_prev, mbuf[p ^ 1][w ^ 1]);
            m_prev = m;
            const int E = (__float_as_int(comb) >> 23) & 0xFF;
            int se = 187 - E - se_ap;
            se = min(max(se, 0), 63);
            se_ap = se;
            sc_ap = __int_as_float((se + 127) << 23);
        }
    }

    // ================= phase 2: t = 65..320 (select-free body) =============
    float cinj = aMI0 * inj;                    // mprev == inj for t >= 2
#pragma unroll 8
    for (int t = 65; t <= L + K; ++t) {
        float Mn = P * fmaf(aDM, qD, fmaf(aIM, qI, aMM * qM));
        float In = fmaf(aII, cI, aMI * cM);
        float Dn = fmaf(aDD, nD, aMD * nM);

        qM = nM; qI = nI; qD = nD;
        cM = Mn; cI = In; cD = Dn;

        k0I = fmaf(aII0, k0I, cinj);

        nM = __shfl_up_sync(FULLMASK, cM, 1);
        nI = __shfl_up_sync(FULLMASK, cI, 1);
        nD = __shfl_up_sync(FULLMASK, cD, 1);
        if (tid == 31) bbuf[t & 1] = make_float4(cM, cI, cD, 0.f);
        __syncthreads();
        if (tid == 0)        { nM = inj; nI = k0I; nD = inj; }
        else if (tid == 32)  { float4 v = bbuf[t & 1]; nM = v.x; nI = v.y; nD = v.z; }

        P = esh[off_p + gk];
        off_p = s_co_p[t - gk + 64];

        if ((t & 3) == 0) {
            cM *= sc_ap; cI *= sc_ap; cD *= sc_ap;
            qM *= sc_ap; qI *= sc_ap; qD *= sc_ap;
            nM *= sc_ap; nI *= sc_ap; nD *= sc_ap;
            k0I *= sc_ap; inj *= sc_ap; cinj *= sc_ap;
            Sacc += se_ap;
            float m = fmaxf(fmaxf(cM, cI), fmaxf(cD, k0I));
            m = __uint_as_float(warp_max_u32(__float_as_uint(m)));
            const int p = (t >> 2) & 1;
            if (lane == 0) mbuf[p][w] = m;
            const float comb = fmaxf(m_prev, mbuf[p ^ 1][w ^ 1]);
            m_prev = m;
            const int E = (__float_as_int(comb) >> 23) & 0xFF;
            int se = 187 - E - se_ap;
            se = min(max(se, 0), 63);
            se_ap = se;
            sc_ap = __int_as_float((se + 127) << 23);
        }
    }

    // warp B lane 31 holds (M, I, D) at (L, K)
    if (w == 1) {
        const float MF = __shfl_sync(FULLMASK, cM, 31);
        const float IF = __shfl_sync(FULLMASK, cI, 31);
        const float DF = __shfl_sync(FULLMASK, cD, 31);
        const float fM = expf(a[K * 7 + 0]);
        const float fI = expf(a[K * 7 + 3]);
        const float fD = expf(a[K * 7 + 5]);
        const float sum = fmaf(fD, DF, fmaf(fI, IF, fM * MF));
        const float nll = -(log2f(sum) - (float)Sacc) * LN2;

        // KLD term: -0.5 * sum_e (1 + lv - mu^2 - exp(lv))
        float term = 0.0f;
        if (lane < 16) {
            const float mu = mus[b * 16 + lane];
            const float lv = logvars[b * 16 + lane];
            term = 1.0f + lv - mu * mu - expf(lv);
        }
#pragma unroll
        for (int o = 16; o > 0; o >>= 1) term += __shfl_xor_sync(FULLMASK, term, o);

        if (lane == 0) g_vb[b] = nll - 0.5f * term;

        // ---- last-block-done final reduction (deterministic fixed order) ----
        __threadfence();
        unsigned int old = 0;
        if (lane == 0) old = atomicAdd(&g_cnt, 1u);
        old = __shfl_sync(FULLMASK, old, 0);
        if (old == gridDim.x - 1) {
            __threadfence();
            float s = 0.0f;
#pragma unroll
            for (int i = 0; i < 16; ++i) s += g_vb[lane + 32 * i];
#pragma unroll
            for (int o = 16; o > 0; o >>= 1) s += __shfl_xor_sync(FULLMASK, s, o);
            if (lane == 0) { out[0] = s * (1.0f / 512.0f); g_cnt = 0; }
        }
    }
}

extern "C" void kernel_launch(void* const* d_in, const int* in_sizes, int n_in,
                              void* d_out, int out_size) {
    const int*   batch_input = (const int*)  d_in[0];
    const float* trans       = (const float*)d_in[1];
    const float* emisp       = (const float*)d_in[2];
    const float* mus         = (const float*)d_in[3];
    const float* logvars     = (const float*)d_in[4];
    (void)in_sizes; (void)n_in; (void)out_size;

    phmm_kernel<<<512, 64>>>(batch_input, trans, emisp, mus, logvars, (float*)d_out);
}

// round 14
// speedup vs baseline: 2.4211x; 2.4211x over previous
#include <cuda_runtime.h>

// Profile-HMM forward NLL + KLD -- wavefront, scaled linear domain.
// 512 one-warp blocks (R12 base). Lane owns k = 2*lane+1, 2*lane+2.
// D-chain shortened algebraically: slot2's D uses cD1 re-expressed in the
// two-shuffle-old q registers (cD1 = aMD1*qM + aDD1*qD), so the
// shfl->D->shfl cycle spans two iterations instead of one.

#define FULLMASK 0xffffffffu
#define LN2 0.69314718055994531f

__device__ float g_vb[512];
__device__ unsigned int g_cnt = 0;

__device__ __forceinline__ unsigned warp_max_u32(unsigned v) {
    unsigned r;
    asm volatile("redux.sync.max.u32 %0, %1, 0xffffffff;" : "=r"(r) : "r"(v));
    return r;
}

__global__ void __launch_bounds__(32) phmm_kernel(
    const int*   __restrict__ binput,    // (B, 256)
    const float* __restrict__ trans,     // (B, 65, 7) log-probs (nats)
    const float* __restrict__ emis,      // (B, 64, 4) log-probs (nats)
    const float* __restrict__ mus,       // (B, 16)
    const float* __restrict__ logvars,   // (B, 16)
    float*       __restrict__ out)
{
    constexpr int L = 256;
    constexpr int K = 64;
    const int b    = blockIdx.x;
    const int lane = threadIdx.x;

    __shared__ int    s_co_p[416];       // 64 front-pad + 256 symbols + pad
    __shared__ float2 ep[128];           // [4 symbols][32 lanes] {e1, e2}

    const int* bi = binput + b * L;
#pragma unroll
    for (int i = 0; i < 13; ++i) {
        const int idx = lane + 32 * i;
        int v = 0;
        if (idx >= 64 && idx < 320) v = bi[idx - 64] << 5;
        s_co_p[idx] = v;
    }

    const float* a  = trans + b * 65 * 7;
    const float* em = emis  + b * 64 * 4;

    const int k1 = 2 * lane + 1;
    const float* r0 = a + (k1 - 1) * 7;  // transition row k1-1
    const float* r1 = r0 + 7;            // row k1 (= row k2-1)
    const float* r2 = r1 + 7;            // row k2

    // M2M=0, M2I=1, M2D=2, I2M=3, I2I=4, D2M=5, D2D=6; LOG_Q folded.
    const float aMM1 = expf(r0[0]), aMD1 = expf(r0[2]);
    const float aIM1 = expf(r0[3]), aDM1 = expf(r0[5]), aDD1 = expf(r0[6]);
    const float aMI1 = 0.25f * expf(r1[1]), aII1 = 0.25f * expf(r1[4]);
    const float aMM2 = expf(r1[0]), aMD2 = expf(r1[2]);
    const float aIM2 = expf(r1[3]), aDM2 = expf(r1[5]), aDD2 = expf(r1[6]);
    const float aMI2 = 0.25f * expf(r2[1]), aII2 = 0.25f * expf(r2[4]);
    const float aMI0 = 0.25f * expf(a[1]),  aII0 = 0.25f * expf(a[4]);
    // constant products for the D2 substitution
    const float cDM = aDD2 * aMD1, cDD = aDD2 * aDD1;

#pragma unroll
    for (int c = 0; c < 4; ++c)
        ep[c * 32 + lane] = make_float2(expf(em[(k1 - 1) * 4 + c]),
                                        expf(em[k1 * 4 + c]));
    __syncwarp();

    float cM1 = 0.f, cI1 = 0.f, cD1 = 0.f, pM1 = 0.f, pI1 = 0.f, pD1 = 0.f;
    float cM2 = 0.f, cI2 = 0.f, cD2 = 0.f;
    const float M00 = 1.152921504606847e18f;    // 1.0 * 2^60
    float inj   = exp2f(-84.26950408889634f);   // e^-100 * 2^60
    float k0I   = inj;
    float mprev = M00;
    int   Sacc  = 60;
    float sc_ap = 1.0f;  int se_ap = 0;

    float nM = (lane == 0) ? M00 : 0.f;
    float nI = (lane == 0) ? inj : 0.f;
    float nD = (lane == 0) ? inj : 0.f;
    float qM = 0.f, qI = 0.f, qD = 0.f;

    int    off_p = s_co_p[65 - k1];
    float2 P     = ep[s_co_p[64 - k1] + lane];
    float  e2c   = 0.0f;

    // ================= phase 1: t = 1..64 (boundary forcing live) ==========
#pragma unroll 4
    for (int t = 1; t <= 64; ++t) {
        const float e1 = P.x;
        const float e2 = e2c;
        const int l1 = t - k1;

        float M1g = e1 * fmaf(aDM1, qD, fmaf(aIM1, qI, aMM1 * qM));
        float I1g = fmaf(aII1, cI1, aMI1 * cM1);
        float D1n = fmaf(aDD1, nD, aMD1 * nM);
        // D2 via substitution: cD1 == aMD1*qM + aDD1*qD (post-fixup q)
        float D2n = fmaf(aMD2, cM1, fmaf(cDM, qM, cDD * qD));
        float M1n = (l1 == 0) ? inj : M1g;
        float I1n = (l1 == 0) ? inj : I1g;

        float M2g = e2 * fmaf(aDM2, pD1, fmaf(aIM2, pI1, aMM2 * pM1));
        float I2g = fmaf(aII2, cI2, aMI2 * cM2);
        float M2n = (l1 == 1) ? inj : M2g;
        float I2n = (l1 == 1) ? inj : I2g;

        cM2 = M2n; cI2 = I2n; cD2 = D2n;
        pM1 = cM1; pI1 = cI1; pD1 = cD1; cM1 = M1n; cI1 = I1n; cD1 = D1n;
        qM = nM; qI = nI; qD = nD;

        k0I = fmaf(aII0, k0I, aMI0 * mprev);
        mprev = inj;

        nM = __shfl_up_sync(FULLMASK, cM2, 1);
        nI = __shfl_up_sync(FULLMASK, cI2, 1);
        nD = __shfl_up_sync(FULLMASK, cD2, 1);
        if (lane == 0) { nM = mprev; nI = k0I; nD = inj; }

        e2c = P.y;
        P = ep[off_p + lane];
        off_p = s_co_p[t - k1 + 65];

        if ((t & 3) == 0) {
            cM1 *= sc_ap; cI1 *= sc_ap; cD1 *= sc_ap;
            pM1 *= sc_ap; pI1 *= sc_ap; pD1 *= sc_ap;
            cM2 *= sc_ap; cI2 *= sc_ap; cD2 *= sc_ap;
            nM  *= sc_ap; nI  *= sc_ap; nD  *= sc_ap;
            qM  *= sc_ap; qI  *= sc_ap; qD  *= sc_ap;
            k0I *= sc_ap; mprev *= sc_ap; inj *= sc_ap;
            Sacc += se_ap;
            float m = fmaxf(fmaxf(cM1, cM2), fmaxf(cI1, cI2));
            m = fmaxf(m, fmaxf(cD1, cD2));
            m = fmaxf(m, k0I);
            const unsigned mu32 = warp_max_u32(__float_as_uint(m));
            const int E = (int)(mu32 >> 23) & 0xFF;
            int se = 187 - E;
            se = min(max(se, 0), 63);
            se_ap = se;
            sc_ap = __int_as_float((se + 127) << 23);
        }
    }

    // ================= phase 2: t = 65..320 (select-free body) =============
    float cinj = aMI0 * inj;                    // mprev == inj for t >= 2
#pragma unroll 8
    for (int t = 65; t <= L + K; ++t) {
        const float e1 = P.x;
        const float e2 = e2c;

        float M1n = e1 * fmaf(aDM1, qD, fmaf(aIM1, qI, aMM1 * qM));
        float I1n = fmaf(aII1, cI1, aMI1 * cM1);
        float D1n = fmaf(aDD1, nD, aMD1 * nM);
        float D2n = fmaf(aMD2, cM1, fmaf(cDM, qM, cDD * qD));

        float M2n = e2 * fmaf(aDM2, pD1, fmaf(aIM2, pI1, aMM2 * pM1));
        float I2n = fmaf(aII2, cI2, aMI2 * cM2);

        cM2 = M2n; cI2 = I2n; cD2 = D2n;
        pM1 = cM1; pI1 = cI1; pD1 = cD1; cM1 = M1n; cI1 = I1n; cD1 = D1n;
        qM = nM; qI = nI; qD = nD;

        k0I = fmaf(aII0, k0I, cinj);

        nM = __shfl_up_sync(FULLMASK, cM2, 1);
        nI = __shfl_up_sync(FULLMASK, cI2, 1);
        nD = __shfl_up_sync(FULLMASK, cD2, 1);
        if (lane == 0) { nM = inj; nI = k0I; nD = inj; }

        e2c = P.y;
        P = ep[off_p + lane];
        off_p = s_co_p[t - k1 + 65];

        if ((t & 3) == 0) {
            cM1 *= sc_ap; cI1 *= sc_ap; cD1 *= sc_ap;
            pM1 *= sc_ap; pI1 *= sc_ap; pD1 *= sc_ap;
            cM2 *= sc_ap; cI2 *= sc_ap; cD2 *= sc_ap;
            nM  *= sc_ap; nI  *= sc_ap; nD  *= sc_ap;
            qM  *= sc_ap; qI  *= sc_ap; qD  *= sc_ap;
            k0I *= sc_ap; inj *= sc_ap; cinj *= sc_ap;
            Sacc += se_ap;
            float m = fmaxf(fmaxf(cM1, cM2), fmaxf(cI1, cI2));
            m = fmaxf(m, fmaxf(cD1, cD2));
            m = fmaxf(m, k0I);
            const unsigned mu32 = warp_max_u32(__float_as_uint(m));
            const int E = (int)(mu32 >> 23) & 0xFF;
            int se = 187 - E;
            se = min(max(se, 0), 63);
            se_ap = se;
            sc_ap = __int_as_float((se + 127) << 23);
        }
    }

    // lane 31 slot2 holds (M, I, D) at (L, K)
    const float MF = __shfl_sync(FULLMASK, cM2, 31);
    const float IF = __shfl_sync(FULLMASK, cI2, 31);
    const float DF = __shfl_sync(FULLMASK, cD2, 31);
    const float fM = expf(a[K * 7 + 0]);
    const float fI = expf(a[K * 7 + 3]);
    const float fD = expf(a[K * 7 + 5]);
    const float sum = fmaf(fD, DF, fmaf(fI, IF, fM * MF));
    const float nll = -(log2f(sum) - (float)Sacc) * LN2;

    float term = 0.0f;
    if (lane < 16) {
        const float mu = mus[b * 16 + lane];
        const float lv = logvars[b * 16 + lane];
        term = 1.0f + lv - mu * mu - expf(lv);
    }
#pragma unroll
    for (int o = 16; o > 0; o >>= 1) term += __shfl_xor_sync(FULLMASK, term, o);

    if (lane == 0) g_vb[b] = nll - 0.5f * term;

    // ---- last-block-done final reduction (deterministic fixed-order sum) ----
    __threadfence();
    unsigned int old = 0;
    if (lane == 0) old = atomicAdd(&g_cnt, 1u);
    old = __shfl_sync(FULLMASK, old, 0);
    if (old == gridDim.x - 1) {
        __threadfence();
        float s = 0.0f;
#pragma unroll
        for (int i = 0; i < 16; ++i) s += g_vb[lane + 32 * i];
#pragma unroll
        for (int o = 16; o > 0; o >>= 1) s += __shfl_xor_sync(FULLMASK, s, o);
        if (lane == 0) { out[0] = s * (1.0f / 512.0f); g_cnt = 0; }
    }
}

extern "C" void kernel_launch(void* const* d_in, const int* in_sizes, int n_in,
                              void* d_out, int out_size) {
    const int*   batch_input = (const int*)  d_in[0];
    const float* trans       = (const float*)d_in[1];
    const float* emisp       = (const float*)d_in[2];
    const float* mus         = (const float*)d_in[3];
    const float* logvars     = (const float*)d_in[4];
    (void)in_sizes; (void)n_in; (void)out_size;

    phmm_kernel<<<512, 32>>>(batch_input, trans, emisp, mus, logvars, (float*)d_out);
}